// round 15
// baseline (speedup 1.0000x reference)
#include <cuda_runtime.h>
#include <cstdint>

// NATTEN 7x7, B=2, heads=8, d=32, 56x56, fp32.
// x: (B,768,56,56) qkv-packed; rpb: (8,13,13); out: (B,256,56,56).
// 224 threads/CTA: lane pair z splits d (16 dims each); each pair handles 4
// vertically-adjacent queries over their 10-row window union (70 taps serve
// 4 queries -> 0.625x crossbar bytes). Fused per-tap QK->ex2->AV, log2-domain,
// batch softmax without max-shift.

#define HH 56
#define WW 56
#define PLANE 3136
#define ROWS 8
#define SROWS 14
#define NT 224
#define CS 36                     // col stride (floats)
#define RB (WW * CS * 4)          // smem row stride in bytes
#define TSLOTS (SROWS * WW)       // 784
#define TELEMS (TSLOTS * CS)      // 28224 floats per tensor
#define LOG2E 1.4426950408889634f

__device__ __forceinline__ uint64_t pack2(float lo, float hi) {
    uint64_t r; asm("mov.b64 %0, {%1,%2};" : "=l"(r) : "f"(lo), "f"(hi)); return r;
}
__device__ __forceinline__ float2 unpack2(uint64_t v) {
    float2 f; asm("mov.b64 {%0,%1}, %2;" : "=f"(f.x), "=f"(f.y) : "l"(v)); return f;
}
__device__ __forceinline__ uint64_t ffma2(uint64_t a, uint64_t b, uint64_t c) {
    uint64_t d; asm("fma.rn.f32x2 %0, %1, %2, %3;" : "=l"(d) : "l"(a), "l"(b), "l"(c)); return d;
}
__device__ __forceinline__ uint64_t fadd2(uint64_t a, uint64_t b) {
    uint64_t d; asm("add.rn.f32x2 %0, %1, %2;" : "=l"(d) : "l"(a), "l"(b)); return d;
}
__device__ __forceinline__ void lds16(uint32_t a, uint64_t& x, uint64_t& y) {
    asm volatile("ld.shared.v2.b64 {%0,%1}, [%2];" : "=l"(x), "=l"(y) : "r"(a));
}
__device__ __forceinline__ float ex2(float x) {
    float y; asm("ex2.approx.f32 %0, %1;" : "=f"(y) : "f"(x)); return y;
}

__global__ __launch_bounds__(NT, 1)
void natten7x7_kernel(const float* __restrict__ x,
                      const float* __restrict__ rpb,
                      float* __restrict__ out)
{
    extern __shared__ float smem[];
    float* ks = smem;                 // [784][36]
    float* vs = smem + TELEMS;
    float* rs = smem + 2 * TELEMS;    // [192] rpb*log2e

    const int bh = blockIdx.y, b = bh >> 3, head = bh & 7;
    const int i0 = blockIdx.x * ROWS;
    const int r0 = min(max(i0 - 3, 0), HH - SROWS);

    const int z  = threadIdx.x;           // 0/1: d-half
    const int j  = threadIdx.y;           // query col
    const int tq = threadIdx.z;           // row-quad 0/1
    const int tid = z + 2 * j + 112 * tq;

    const float* xb = x + (size_t)b * (768 * PLANE);
    const float* kg = xb + (size_t)(256 + head * 32) * PLANE + r0 * WW;
    const float* vg = xb + (size_t)(512 + head * 32) * PLANE + r0 * WW;

    if (tid < 169) rs[tid] = rpb[head * 169 + tid] * LOG2E;

    // ---- transpose-load K/V, division-free slot loader ----
    #pragma unroll
    for (int s = 0; s < 4; s++) {
        const int slot = tid + s * NT;
        if (s < 3 || slot < TSLOTS) {
            float* kd = ks + slot * CS;
            float* vd = vs + slot * CS;
            #pragma unroll
            for (int dblk = 0; dblk < 8; dblk++) {
                const float* pk = kg + dblk * 4 * PLANE + slot;
                const float* pv = vg + dblk * 4 * PLANE + slot;
                *(float4*)(kd + dblk * 4) = make_float4(pk[0], pk[PLANE], pk[2 * PLANE], pk[3 * PLANE]);
                *(float4*)(vd + dblk * 4) = make_float4(pv[0], pv[PLANE], pv[2 * PLANE], pv[3 * PLANE]);
            }
        }
    }

    // ---- load + pack q: this lane's 16 dims for 4 query rows ----
    const int iA = i0 + 4 * tq;
    const float scale = 0.17677669529663687f * LOG2E;
    uint64_t q[4][8];
    {
        const float* qg = xb + (size_t)(head * 32 + 16 * z) * PLANE + iA * WW + j;
        #pragma unroll
        for (int m = 0; m < 4; m++) {
            const float* qm = qg + m * WW;
            #pragma unroll
            for (int t = 0; t < 8; t++)
                q[m][t] = pack2(qm[(2 * t) * PLANE] * scale, qm[(2 * t + 1) * PLANE] * scale);
        }
    }
    __syncthreads();

    // ---- window geometry for the 4 queries ----
    int ni[4], off[4], pi[4];
    #pragma unroll
    for (int m = 0; m < 4; m++) {
        const int im = iA + m;
        ni[m] = min(max(im - 3, 0), HH - 7);
        pi[m] = 6 - (im - ni[m]);
    }
    #pragma unroll
    for (int m = 0; m < 4; m++) off[m] = ni[m] - ni[0];   // 0..3, monotone

    const int nj = min(max(j - 3, 0), WW - 7);
    const int pj = 6 - (j - nj);
    const int rbase = ni[0] - r0;

    const uint32_t sbase = (uint32_t)__cvta_generic_to_shared(ks)
                         + (uint32_t)(nj * CS * 4) + (uint32_t)(z * 64);

    float s[4] = {0.f, 0.f, 0.f, 0.f};
    uint64_t o[4][8];
    #pragma unroll
    for (int m = 0; m < 4; m++)
        #pragma unroll
        for (int t = 0; t < 8; t++) o[m][t] = 0ull;

    // ---- fused pass over the 10-row window union ----
    #pragma unroll
    for (int rr = 0; rr < 10; rr++) {
        const int sr = min(rbase + rr, SROWS - 1);   // clamped rows are all-masked
        const uint32_t rk = sbase + (uint32_t)(sr * RB);
        const uint32_t rv = rk + (uint32_t)(TELEMS * 4);

        // per-query validity + safe bias row pointer
        bool vm[4]; const float* brow[4];
        #pragma unroll
        for (int m = 0; m < 4; m++) {
            vm[m] = (rr >= off[m]) && (rr <= off[m] + 6);
            const int prow = vm[m] ? (pi[m] + rr - off[m]) : 0;   // safe index
            brow[m] = rs + prow * 13 + pj;
        }

        #pragma unroll
        for (int kj = 0; kj < 7; kj++) {
            const uint32_t ak = rk + (uint32_t)(kj * (CS * 4));
            const uint32_t av = rv + (uint32_t)(kj * (CS * 4));
            uint64_t kt[8], vt[8];
            #pragma unroll
            for (int u = 0; u < 4; u++) lds16(ak + 16 * u, kt[2 * u], kt[2 * u + 1]);
            #pragma unroll
            for (int u = 0; u < 4; u++) lds16(av + 16 * u, vt[2 * u], vt[2 * u + 1]);

            float pm[4];
            #pragma unroll
            for (int m = 0; m < 4; m++) {
                uint64_t a0 = ffma2(q[m][0], kt[0], 0ull);
                uint64_t a1 = ffma2(q[m][1], kt[1], 0ull);
                #pragma unroll
                for (int t = 2; t < 8; t += 2) {
                    a0 = ffma2(q[m][t],     kt[t],     a0);
                    a1 = ffma2(q[m][t + 1], kt[t + 1], a1);
                }
                float2 f = unpack2(fadd2(a0, a1));
                pm[m] = f.x + f.y;
            }
            #pragma unroll
            for (int m = 0; m < 4; m++)
                pm[m] += __shfl_xor_sync(0xffffffffu, pm[m], 1);   // full 32-d dot

            #pragma unroll
            for (int m = 0; m < 4; m++) {
                const float bias = vm[m] ? brow[m][kj] : -1e30f;
                const float w = ex2(pm[m] + bias);                  // masked -> exactly 0
                s[m] += w;
                const uint64_t w2 = pack2(w, w);
                #pragma unroll
                for (int t = 0; t < 8; t++) o[m][t] = ffma2(w2, vt[t], o[m][t]);
            }
        }
    }

    // ---- write out: this lane owns dims 16z..16z+15 of 4 queries ----
    float* og = out + (size_t)b * (256 * PLANE)
              + (size_t)(head * 32 + 16 * z) * PLANE + iA * WW + j;
    #pragma unroll
    for (int m = 0; m < 4; m++) {
        const float inv = 1.0f / s[m];
        float* om = og + m * WW;
        #pragma unroll
        for (int t = 0; t < 8; t++) {
            float2 f = unpack2(o[m][t]);
            om[(2 * t) * PLANE]     = f.x * inv;
            om[(2 * t + 1) * PLANE] = f.y * inv;
        }
    }
}

extern "C" void kernel_launch(void* const* d_in, const int* in_sizes, int n_in,
                              void* d_out, int out_size)
{
    const float* x   = (const float*)d_in[0];
    const float* rpb = (const float*)d_in[1];
    float* out = (float*)d_out;

    const int smem_bytes = (2 * TELEMS + 192) * sizeof(float);  // 226,560 B
    cudaFuncSetAttribute(natten7x7_kernel,
                         cudaFuncAttributeMaxDynamicSharedMemorySize, smem_bytes);

    dim3 grid(HH / ROWS, 2 * 8);   // 7 x 16 = 112 CTAs -> single wave
    dim3 block(2, WW, 2);          // 224 threads: (d-half, col, row-quad)
    natten7x7_kernel<<<grid, block, smem_bytes>>>(x, rpb, out);
}

// round 16
// speedup vs baseline: 1.1693x; 1.1693x over previous
#include <cuda_runtime.h>
#include <cstdint>

// NATTEN 7x7, B=2, heads=8, d=32, 56x56, fp32.
// x: (B,768,56,56) qkv-packed; rpb: (8,13,13); out: (B,256,56,56).
// 7-row stripes -> 128 CTAs (vs 112): tests per-SM-work-bound hypothesis.
// 256 threads: t<168 = 3 row-pairs (2 queries each, fused R11 path);
// t in [192,248) = row 6 singles (full-d query each). Fused QK->ex2->AV,
// log2-domain, batch softmax without max-shift.

#define HH 56
#define WW 56
#define PLANE 3136
#define ROWS 7
#define SROWS 13
#define NT 256
#define CS 36
#define RB (WW * CS * 4)          // smem row stride in bytes
#define TSLOTS (SROWS * WW)       // 728
#define TELEMS (TSLOTS * CS)      // 26208 floats per tensor
#define LOG2E 1.4426950408889634f

__device__ __forceinline__ uint64_t pack2(float lo, float hi) {
    uint64_t r; asm("mov.b64 %0, {%1,%2};" : "=l"(r) : "f"(lo), "f"(hi)); return r;
}
__device__ __forceinline__ float2 unpack2(uint64_t v) {
    float2 f; asm("mov.b64 {%0,%1}, %2;" : "=f"(f.x), "=f"(f.y) : "l"(v)); return f;
}
__device__ __forceinline__ uint64_t ffma2(uint64_t a, uint64_t b, uint64_t c) {
    uint64_t d; asm("fma.rn.f32x2 %0, %1, %2, %3;" : "=l"(d) : "l"(a), "l"(b), "l"(c)); return d;
}
__device__ __forceinline__ uint64_t fadd2(uint64_t a, uint64_t b) {
    uint64_t d; asm("add.rn.f32x2 %0, %1, %2;" : "=l"(d) : "l"(a), "l"(b)); return d;
}
__device__ __forceinline__ void lds16(uint32_t a, uint64_t& x, uint64_t& y) {
    asm volatile("ld.shared.v2.b64 {%0,%1}, [%2];" : "=l"(x), "=l"(y) : "r"(a));
}
__device__ __forceinline__ float ex2(float x) {
    float y; asm("ex2.approx.f32 %0, %1;" : "=f"(y) : "f"(x)); return y;
}

__global__ __launch_bounds__(NT, 1)
void natten7x7_kernel(const float* __restrict__ x,
                      const float* __restrict__ rpb,
                      float* __restrict__ out)
{
    extern __shared__ float smem[];
    float* ks = smem;                 // [728][36]
    float* vs = smem + TELEMS;
    float* rs = smem + 2 * TELEMS;    // [192] rpb*log2e

    const int bh = blockIdx.y, b = bh >> 3, head = bh & 7;
    const int i0 = blockIdx.x * ROWS;
    const int r0 = min(max(i0 - 3, 0), HH - SROWS);   // 0..43

    const int t = threadIdx.x;

    const float* xb = x + (size_t)b * (768 * PLANE);
    const float* kg = xb + (size_t)(256 + head * 32) * PLANE + r0 * WW;
    const float* vg = xb + (size_t)(512 + head * 32) * PLANE + r0 * WW;

    if (t < 169) rs[t] = rpb[head * 169 + t] * LOG2E;

    // ---- transpose-load K/V: 728 slots, linear on both sides ----
    #pragma unroll
    for (int s = 0; s < 3; s++) {
        const int slot = t + s * NT;
        if (s < 2 || slot < TSLOTS) {
            float* kd = ks + slot * CS;
            float* vd = vs + slot * CS;
            #pragma unroll
            for (int dblk = 0; dblk < 8; dblk++) {
                const float* pk = kg + dblk * 4 * PLANE + slot;
                const float* pv = vg + dblk * 4 * PLANE + slot;
                *(float4*)(kd + dblk * 4) = make_float4(pk[0], pk[PLANE], pk[2 * PLANE], pk[3 * PLANE]);
                *(float4*)(vd + dblk * 4) = make_float4(pv[0], pv[PLANE], pv[2 * PLANE], pv[3 * PLANE]);
            }
        }
    }

    const float scale = 0.17677669529663687f * LOG2E;
    const bool isPair   = (t < 168);
    const bool isSingle = (t >= 192) && (t < 192 + WW);

    // pair-path ids
    const int pr = isPair ? (t / WW) : 0;          // 0..2
    const int jp = isPair ? (t - pr * WW) : 0;
    const int iA = i0 + 2 * pr, iB = iA + 1;
    // single-path ids
    const int js = isSingle ? (t - 192) : 0;
    const int is = i0 + 6;

    // ---- q loads (gmem; before the one block-wide barrier) ----
    uint64_t qA[16], qB[16];
    if (isPair) {
        const float* qa = xb + (size_t)(head * 32) * PLANE + iA * WW + jp;
        const float* qb = qa + WW;
        #pragma unroll
        for (int k = 0; k < 16; k++) {
            qA[k] = pack2(qa[(2 * k) * PLANE] * scale, qa[(2 * k + 1) * PLANE] * scale);
            qB[k] = pack2(qb[(2 * k) * PLANE] * scale, qb[(2 * k + 1) * PLANE] * scale);
        }
    } else if (isSingle) {
        const float* qa = xb + (size_t)(head * 32) * PLANE + is * WW + js;
        #pragma unroll
        for (int k = 0; k < 16; k++)
            qA[k] = pack2(qa[(2 * k) * PLANE] * scale, qa[(2 * k + 1) * PLANE] * scale);
    }
    __syncthreads();

    if (isPair) {
        // ---- pair path: 2 queries over their 8-row window union (R11 fused) ----
        const int niA = min(max(iA - 3, 0), HH - 7);
        const int niB = min(max(iB - 3, 0), HH - 7);
        const int off = niB - niA;
        const int piA = 6 - (iA - niA);
        const int piB = 6 - (iB - niB);
        const int nj  = min(max(jp - 3, 0), WW - 7);
        const int pj  = 6 - (jp - nj);
        const int rbase = niA - r0;   // <= 6; clamp row is always fully masked

        const uint32_t sbase = (uint32_t)__cvta_generic_to_shared(ks) + (uint32_t)(nj * CS * 4);

        float sA = 0.f, sB = 0.f;
        uint64_t oA[16], oB[16];
        #pragma unroll
        for (int k = 0; k < 16; k++) { oA[k] = 0ull; oB[k] = 0ull; }

        #pragma unroll
        for (int rr = 0; rr < 8; rr++) {
            const int  sr = min(rbase + rr, SROWS - 1);
            const bool vB = off ? (rr >= 1) : (rr <= 6);
            const uint32_t rk = sbase + (uint32_t)(sr * RB);
            const uint32_t rv = rk + (uint32_t)(TELEMS * 4);

            #pragma unroll
            for (int kj = 0; kj < 7; kj++) {
                const uint32_t ak = rk + (uint32_t)(kj * (CS * 4));
                const uint32_t av = rv + (uint32_t)(kj * (CS * 4));
                uint64_t kt[16], vt[16];
                #pragma unroll
                for (int u = 0; u < 8; u++) lds16(ak + 16 * u, kt[2 * u], kt[2 * u + 1]);
                #pragma unroll
                for (int u = 0; u < 8; u++) lds16(av + 16 * u, vt[2 * u], vt[2 * u + 1]);

                if (rr < 7) {
                    uint64_t a0 = ffma2(qA[0], kt[0], 0ull);
                    uint64_t a1 = ffma2(qA[1], kt[1], 0ull);
                    #pragma unroll
                    for (int k = 2; k < 16; k += 2) {
                        a0 = ffma2(qA[k],     kt[k],     a0);
                        a1 = ffma2(qA[k + 1], kt[k + 1], a1);
                    }
                    float2 f = unpack2(fadd2(a0, a1));
                    const float w = ex2(f.x + f.y + rs[(piA + rr) * 13 + pj + kj]);
                    sA += w;
                    const uint64_t w2 = pack2(w, w);
                    #pragma unroll
                    for (int k = 0; k < 16; k++) oA[k] = ffma2(w2, vt[k], oA[k]);
                }
                {
                    uint64_t b0 = ffma2(qB[0], kt[0], 0ull);
                    uint64_t b1 = ffma2(qB[1], kt[1], 0ull);
                    #pragma unroll
                    for (int k = 2; k < 16; k += 2) {
                        b0 = ffma2(qB[k],     kt[k],     b0);
                        b1 = ffma2(qB[k + 1], kt[k + 1], b1);
                    }
                    float2 f = unpack2(fadd2(b0, b1));
                    const float bias = vB ? rs[(piB + rr - off) * 13 + pj + kj] : -1e30f;
                    const float w = ex2(f.x + f.y + bias);
                    sB += w;
                    const uint64_t w2 = pack2(w, w);
                    #pragma unroll
                    for (int k = 0; k < 16; k++) oB[k] = ffma2(w2, vt[k], oB[k]);
                }
            }
        }
        const float invA = 1.0f / sA, invB = 1.0f / sB;

        float* oga = out + (size_t)b * (256 * PLANE) + (size_t)(head * 32) * PLANE + iA * WW + jp;
        float* ogb = oga + WW;
        #pragma unroll
        for (int k = 0; k < 16; k++) {
            float2 fa = unpack2(oA[k]);
            float2 fb = unpack2(oB[k]);
            oga[(2 * k) * PLANE]     = fa.x * invA;
            oga[(2 * k + 1) * PLANE] = fa.y * invA;
            ogb[(2 * k) * PLANE]     = fb.x * invB;
            ogb[(2 * k + 1) * PLANE] = fb.y * invB;
        }
    } else if (isSingle) {
        // ---- single path: 1 query, its own 7x7 window (always fully valid) ----
        const int ni = min(max(is - 3, 0), HH - 7);
        const int nj = min(max(js - 3, 0), WW - 7);
        const int pi = 6 - (is - ni);
        const int pj = 6 - (js - nj);
        const int rbase = ni - r0;    // <= 6, so rbase+6 <= 12: no clamp needed

        const uint32_t sbase = (uint32_t)__cvta_generic_to_shared(ks)
                             + (uint32_t)(((rbase * WW) + nj) * CS * 4);

        float s = 0.f;
        uint64_t o[16];
        #pragma unroll
        for (int k = 0; k < 16; k++) o[k] = 0ull;

        #pragma unroll
        for (int rr = 0; rr < 7; rr++) {
            const uint32_t rk = sbase + (uint32_t)(rr * RB);
            const uint32_t rv = rk + (uint32_t)(TELEMS * 4);
            const float* brow = rs + (pi + rr) * 13 + pj;

            #pragma unroll
            for (int kj = 0; kj < 7; kj++) {
                const uint32_t ak = rk + (uint32_t)(kj * (CS * 4));
                const uint32_t av = rv + (uint32_t)(kj * (CS * 4));
                uint64_t kt[16], vt[16];
                #pragma unroll
                for (int u = 0; u < 8; u++) lds16(ak + 16 * u, kt[2 * u], kt[2 * u + 1]);
                #pragma unroll
                for (int u = 0; u < 8; u++) lds16(av + 16 * u, vt[2 * u], vt[2 * u + 1]);

                uint64_t a0 = ffma2(qA[0], kt[0], 0ull);
                uint64_t a1 = ffma2(qA[1], kt[1], 0ull);
                #pragma unroll
                for (int k = 2; k < 16; k += 2) {
                    a0 = ffma2(qA[k],     kt[k],     a0);
                    a1 = ffma2(qA[k + 1], kt[k + 1], a1);
                }
                float2 f = unpack2(fadd2(a0, a1));
                const float w = ex2(f.x + f.y + brow[kj]);
                s += w;
                const uint64_t w2 = pack2(w, w);
                #pragma unroll
                for (int k = 0; k < 16; k++) o[k] = ffma2(w2, vt[k], o[k]);
            }
        }
        const float inv = 1.0f / s;

        float* og = out + (size_t)b * (256 * PLANE) + (size_t)(head * 32) * PLANE + is * WW + js;
        #pragma unroll
        for (int k = 0; k < 16; k++) {
            float2 f = unpack2(o[k]);
            og[(2 * k) * PLANE]     = f.x * inv;
            og[(2 * k + 1) * PLANE] = f.y * inv;
        }
    }
}

extern "C" void kernel_launch(void* const* d_in, const int* in_sizes, int n_in,
                              void* d_out, int out_size)
{
    const float* x   = (const float*)d_in[0];
    const float* rpb = (const float*)d_in[1];
    float* out = (float*)d_out;

    const int smem_bytes = (2 * TELEMS + 192) * sizeof(float);  // 210,432 B
    cudaFuncSetAttribute(natten7x7_kernel,
                         cudaFuncAttributeMaxDynamicSharedMemorySize, smem_bytes);

    dim3 grid(HH / ROWS, 2 * 8);   // 8 x 16 = 128 CTAs -> single wave on 148 SMs
    dim3 block(NT);                // 256 threads: 168 pair + 24 pad + 56 single + 8 pad
    natten7x7_kernel<<<grid, block, smem_bytes>>>(x, rpb, out);
}

// round 17
// speedup vs baseline: 1.2577x; 1.0756x over previous
#include <cuda_runtime.h>
#include <cuda_fp16.h>
#include <cstdint>

// NATTEN 7x7, B=2, heads=8, d=32, 56x56, fp32.
// x: (B,768,56,56) qkv-packed; rpb: (8,13,13); out: (B,256,56,56).
// 224 threads/CTA, 2 vertically-adjacent queries/thread, 8-row stripe.
// Two-pass, log2-domain, fp16x2 weight storage. NEW: V tile is streamed from
// gmem DURING pass 1 (one 4-LDG chunk per tap, STS 6 taps later), hiding the
// V half of the loader prologue behind QK compute.

#define HH 56
#define WW 56
#define PLANE 3136
#define ROWS 8
#define SROWS 14
#define NT 224
#define CS 36
#define RB (WW * CS * 4)          // smem row stride in bytes
#define TSLOTS (SROWS * WW)       // 784
#define TELEMS (TSLOTS * CS)      // 28224 floats per tensor
#define LOG2E 1.4426950408889634f
#define VDEPTH 6                  // V-pipeline stage depth (taps)

__device__ __forceinline__ uint64_t pack2(float lo, float hi) {
    uint64_t r; asm("mov.b64 %0, {%1,%2};" : "=l"(r) : "f"(lo), "f"(hi)); return r;
}
__device__ __forceinline__ float2 unpack2(uint64_t v) {
    float2 f; asm("mov.b64 {%0,%1}, %2;" : "=f"(f.x), "=f"(f.y) : "l"(v)); return f;
}
__device__ __forceinline__ uint64_t ffma2(uint64_t a, uint64_t b, uint64_t c) {
    uint64_t d; asm("fma.rn.f32x2 %0, %1, %2, %3;" : "=l"(d) : "l"(a), "l"(b), "l"(c)); return d;
}
__device__ __forceinline__ uint64_t fadd2(uint64_t a, uint64_t b) {
    uint64_t d; asm("add.rn.f32x2 %0, %1, %2;" : "=l"(d) : "l"(a), "l"(b)); return d;
}
__device__ __forceinline__ void lds16(uint32_t a, uint64_t& x, uint64_t& y) {
    asm volatile("ld.shared.v2.b64 {%0,%1}, [%2];" : "=l"(x), "=l"(y) : "r"(a));
}
__device__ __forceinline__ float ex2(float x) {
    float y; asm("ex2.approx.f32 %0, %1;" : "=f"(y) : "f"(x)); return y;
}

__global__ __launch_bounds__(NT, 1)
void natten7x7_kernel(const float* __restrict__ x,
                      const float* __restrict__ rpb,
                      float* __restrict__ out)
{
    extern __shared__ float smem[];
    float* ks = smem;                 // [784][36]
    float* vs = smem + TELEMS;
    float* rs = smem + 2 * TELEMS;    // [192] rpb*log2e (pad covers guarded idx <= 181)

    const int bh = blockIdx.y, b = bh >> 3, head = bh & 7;
    const int i0 = blockIdx.x * ROWS;
    const int r0 = min(max(i0 - 3, 0), HH - SROWS);

    const int tx = threadIdx.x, ty = threadIdx.y;
    const int tid = ty * WW + tx;
    const bool has4 = (tid < TSLOTS - 3 * NT);    // tid < 112: owns a 4th slot

    const float* xb = x + (size_t)b * (768 * PLANE);
    const float* kg = xb + (size_t)(256 + head * 32) * PLANE + r0 * WW;
    const float* vg = xb + (size_t)(512 + head * 32) * PLANE + r0 * WW;

    if (tid < 169) rs[tid] = rpb[head * 169 + tid] * LOG2E;

    // ---- prologue loads ONLY K (V streams in during pass 1) ----
    #pragma unroll
    for (int s = 0; s < 4; s++) {
        const int slot = tid + s * NT;
        if (s < 3 || has4) {
            float* kd = ks + slot * CS;
            #pragma unroll
            for (int dblk = 0; dblk < 8; dblk++) {
                const float* pk = kg + dblk * 4 * PLANE + slot;
                *(float4*)(kd + dblk * 4) = make_float4(pk[0], pk[PLANE], pk[2 * PLANE], pk[3 * PLANE]);
            }
        }
    }

    // ---- load + pack q for both rows (scale includes log2e) ----
    const int iA = i0 + 2 * ty, iB = iA + 1, j = tx;
    const float scale = 0.17677669529663687f * LOG2E;
    uint64_t qA[16], qB[16];
    {
        const float* qa = xb + (size_t)(head * 32) * PLANE + iA * WW + j;
        const float* qb = qa + WW;
        #pragma unroll
        for (int t = 0; t < 16; t++) {
            qA[t] = pack2(qa[(2 * t) * PLANE] * scale, qa[(2 * t + 1) * PLANE] * scale);
            qB[t] = pack2(qb[(2 * t) * PLANE] * scale, qb[(2 * t + 1) * PLANE] * scale);
        }
    }
    __syncthreads();   // barrier 1: K tile + rpb ready

    // ---- window geometry ----
    const int niA = min(max(iA - 3, 0), HH - 7);
    const int niB = min(max(iB - 3, 0), HH - 7);
    const int off = niB - niA;
    const int piA = 6 - (iA - niA);
    const int piB = 6 - (iB - niB);
    const int nj  = min(max(j - 3, 0), WW - 7);
    const int pj  = 6 - (j - nj);
    const int rbase = niA - r0;   // 0..7 (7 only in edge stripes, where off==0)

    const uint32_t sbase = (uint32_t)__cvta_generic_to_shared(ks) + (uint32_t)(nj * CS * 4);

    int srow[8];
    #pragma unroll
    for (int rr = 0; rr < 8; rr++) srow[rr] = min(rbase + rr, SROWS - 1);

    // ---- pass 1: QK -> ex2 (fp16x2 weights), V tile streaming interleaved ----
    __half2 pAh[25], pBh[28];
    float pendA = 0.f, pendB = 0.f;
    float sA = 0.f, sB = 0.f;
    float4 vstage[VDEPTH];

    #pragma unroll
    for (int rr = 0; rr < 8; rr++) {
        const bool vB = off ? (rr >= 1) : (rr <= 6);
        #pragma unroll
        for (int kj = 0; kj < 7; kj++) {
            const int tap = rr * 7 + kj;      // compile-time after full unroll

            // -- V pipeline: STS chunk (tap-VDEPTH), then LDG chunk (tap) --
            {
                const int cst = tap - VDEPTH;
                if (cst >= 0 && cst < 32) {
                    const int s = cst >> 3, dblk = cst & 7;
                    const int slot = tid + s * NT;
                    if (s < 3 || has4)
                        *(float4*)(vs + slot * CS + dblk * 4) = vstage[cst % VDEPTH];
                }
                if (tap < 32) {
                    const int s = tap >> 3, dblk = tap & 7;
                    const int slot = tid + s * NT;
                    if (s < 3 || has4) {
                        const float* p = vg + dblk * 4 * PLANE + slot;
                        vstage[tap % VDEPTH] = make_float4(p[0], p[PLANE], p[2 * PLANE], p[3 * PLANE]);
                    }
                }
            }

            // -- QK dot for both queries (d-halved 16-reg kt window) --
            const uint32_t a = sbase + (uint32_t)(srow[rr] * RB) + (uint32_t)(kj * (CS * 4));
            uint64_t a0 = 0ull, a1 = 0ull, b0 = 0ull, b1 = 0ull;
            #pragma unroll
            for (int h = 0; h < 2; h++) {
                uint64_t kt[8];
                #pragma unroll
                for (int u = 0; u < 4; u++) lds16(a + 64 * h + 16 * u, kt[2 * u], kt[2 * u + 1]);
                #pragma unroll
                for (int t = 0; t < 8; t += 2) {
                    if (rr < 7) {
                        a0 = ffma2(qA[8 * h + t],     kt[t],     a0);
                        a1 = ffma2(qA[8 * h + t + 1], kt[t + 1], a1);
                    }
                    b0 = ffma2(qB[8 * h + t],     kt[t],     b0);
                    b1 = ffma2(qB[8 * h + t + 1], kt[t + 1], b1);
                }
            }
            if (rr < 7) {
                float2 f = unpack2(fadd2(a0, a1));
                const float w = ex2(f.x + f.y + rs[(piA + rr) * 13 + pj + kj]);
                sA += w;
                if (tap & 1) pAh[tap >> 1] = __floats2half2_rn(pendA, w);
                else         pendA = w;
            }
            {
                float2 f = unpack2(fadd2(b0, b1));
                const float bias = vB ? rs[(piB + rr - off) * 13 + pj + kj] : -1e30f;
                const float w = ex2(f.x + f.y + bias);
                sB += w;
                if (tap & 1) pBh[tap >> 1] = __floats2half2_rn(pendB, w);
                else         pendB = w;
            }
        }
    }
    pAh[24] = __floats2half2_rn(pendA, 0.f);   // A has 49 taps (odd count)
    const float invA = 1.0f / sA, invB = 1.0f / sB;

    __syncthreads();   // barrier 2: V tile ready

    // ---- pass 2: AV (shared V reads feed both queries) ----
    const uint32_t vbase = sbase + (uint32_t)(TELEMS * 4);
    uint64_t oA[16], oB[16];
    #pragma unroll
    for (int t = 0; t < 16; t++) { oA[t] = 0ull; oB[t] = 0ull; }
    #pragma unroll
    for (int rr = 0; rr < 8; rr++) {
        #pragma unroll
        for (int kj = 0; kj < 7; kj++) {
            const uint32_t a = vbase + (uint32_t)(srow[rr] * RB) + (uint32_t)(kj * (CS * 4));
            const int tap = rr * 7 + kj;

            uint64_t wA2 = 0ull, wB2 = 0ull;
            if (rr < 7) {
                float2 f2 = __half22float2(pAh[tap >> 1]);
                const float w = (tap & 1) ? f2.y : f2.x;
                wA2 = pack2(w, w);
            }
            {
                float2 f2 = __half22float2(pBh[tap >> 1]);
                const float w = (tap & 1) ? f2.y : f2.x;   // masked entries exactly 0
                wB2 = pack2(w, w);
            }

            #pragma unroll
            for (int h = 0; h < 2; h++) {
                uint64_t vt[8];
                #pragma unroll
                for (int u = 0; u < 4; u++) lds16(a + 64 * h + 16 * u, vt[2 * u], vt[2 * u + 1]);
                #pragma unroll
                for (int t = 0; t < 8; t++) {
                    if (rr < 7) oA[8 * h + t] = ffma2(wA2, vt[t], oA[8 * h + t]);
                    oB[8 * h + t] = ffma2(wB2, vt[t], oB[8 * h + t]);
                }
            }
        }
    }

    // ---- write out (B,256,56,56) ----
    float* oga = out + (size_t)b * (256 * PLANE) + (size_t)(head * 32) * PLANE + iA * WW + j;
    float* ogb = oga + WW;
    #pragma unroll
    for (int t = 0; t < 16; t++) {
        float2 fa = unpack2(oA[t]);
        float2 fb = unpack2(oB[t]);
        oga[(2 * t) * PLANE]     = fa.x * invA;
        oga[(2 * t + 1) * PLANE] = fa.y * invA;
        ogb[(2 * t) * PLANE]     = fb.x * invB;
        ogb[(2 * t + 1) * PLANE] = fb.y * invB;
    }
}

extern "C" void kernel_launch(void* const* d_in, const int* in_sizes, int n_in,
                              void* d_out, int out_size)
{
    const float* x   = (const float*)d_in[0];
    const float* rpb = (const float*)d_in[1];
    float* out = (float*)d_out;

    const int smem_bytes = (2 * TELEMS + 192) * sizeof(float);  // 226,560 B
    cudaFuncSetAttribute(natten7x7_kernel,
                         cudaFuncAttributeMaxDynamicSharedMemorySize, smem_bytes);

    dim3 grid(HH / ROWS, 2 * 8);   // 7 x 16 = 112 CTAs -> single wave
    dim3 block(WW, 4);             // 224 threads, each owns 2 query rows
    natten7x7_kernel<<<grid, block, smem_bytes>>>(x, rpb, out);
}